// round 13
// baseline (speedup 1.0000x reference)
#include <cuda_runtime.h>
#include <cuda_bf16.h>
#include <math.h>
#include <stdint.h>

#define BATCH 4096
#define NTAB 26
#define VOCAB 100000
#define EMBD 64
#define NT1 27
#define NPAIR 351
#define RDIM 415
#define RP 208            // pairs per R row
#define SROW 36           // interact smem row stride (u32)
#define SROWG 20          // gemm smem row stride (u32): 16 pairs + 4 pad

// ---- pre-split weight / input buffers (hi/lo bf16x2 pairs) ----
__device__ uint32_t g_dxh[BATCH * 8],  g_dxl[BATCH * 8];
__device__ uint32_t g_w0h[512 * 8],    g_w0l[512 * 8];
__device__ uint32_t g_w1h[256 * 256],  g_w1l[256 * 256];
__device__ uint32_t g_w2h[64 * 128],   g_w2l[64 * 128];
__device__ uint32_t g_t0h[512 * 208],  g_t0l[512 * 208];
__device__ uint32_t g_t1h[256 * 256],  g_t1l[256 * 256];
// ---- split activations / embedding rows ----
__device__ uint32_t g_x1h[BATCH * 256], g_x1l[BATCH * 256];
__device__ uint32_t g_x2h[BATCH * 128], g_x2l[BATCH * 128];
__device__ uint32_t g_x3h[BATCH * 32],  g_x3l[BATCH * 32];
__device__ uint32_t g_Th [BATCH * NTAB * 32], g_Tl[BATCH * NTAB * 32];
__device__ uint32_t g_Rh [BATCH * RP],  g_Rl [BATCH * RP];
__device__ uint32_t g_z1h[BATCH * 256], g_z1l[BATCH * 256];

__device__ __forceinline__ uint32_t pack_bf16x2(float lo, float hi)
{
    __nv_bfloat162 p = __floats2bfloat162_rn(lo, hi);
    return *reinterpret_cast<uint32_t*>(&p);
}
__device__ __forceinline__ float bf16_round(float v)
{
    return __bfloat162float(__float2bfloat16(v));
}
__device__ __forceinline__ void mma_bf16(float* c, const uint32_t* a, const uint32_t* b)
{
    asm volatile(
        "mma.sync.aligned.m16n8k16.row.col.f32.bf16.bf16.f32 "
        "{%0,%1,%2,%3}, {%4,%5,%6,%7}, {%8,%9}, {%0,%1,%2,%3};"
        : "+f"(c[0]), "+f"(c[1]), "+f"(c[2]), "+f"(c[3])
        : "r"(a[0]), "r"(a[1]), "r"(a[2]), "r"(a[3]), "r"(b[0]), "r"(b[1]));
}
__device__ __forceinline__ void ldm_x4(uint32_t* r, const uint32_t* p)
{
    uint32_t a = (uint32_t)__cvta_generic_to_shared(p);
    asm volatile("ldmatrix.sync.aligned.m8n8.x4.shared.b16 {%0,%1,%2,%3}, [%4];"
        : "=r"(r[0]), "=r"(r[1]), "=r"(r[2]), "=r"(r[3]) : "r"(a));
}
__device__ __forceinline__ void cp16(const uint32_t* dst, const uint32_t* src, int bytes)
{
    uint32_t d = (uint32_t)__cvta_generic_to_shared(dst);
    asm volatile("cp.async.cg.shared.global [%0], [%1], 16, %2;\n"
                 :: "r"(d), "l"(src), "r"(bytes));
}
__device__ __forceinline__ void cp_commit() { asm volatile("cp.async.commit_group;\n"); }
template<int N>
__device__ __forceinline__ void cp_wait() { asm volatile("cp.async.wait_group %0;\n" :: "n"(N)); }

// ---------------------------------------------------------------------------
// Split dense_x + 5 weight matrices into bf16 hi/lo pair arrays.
// ---------------------------------------------------------------------------
__global__ __launch_bounds__(256)
void split_all(const float* __restrict__ dx, const float* __restrict__ w0,
               const float* __restrict__ w1, const float* __restrict__ w2,
               const float* __restrict__ t0, const float* __restrict__ t1)
{
    int i = blockIdx.x * 256 + threadIdx.x;
    if (i >= 282624) return;
    const float* src; uint32_t *dh, *dl; int K, P, local;
    if (i < 32768)       { src = dx; dh = g_dxh; dl = g_dxl; K = 13;  P = 8;   local = i; }
    else if (i < 36864)  { src = w0; dh = g_w0h; dl = g_w0l; K = 13;  P = 8;   local = i - 32768; }
    else if (i < 102400) { src = w1; dh = g_w1h; dl = g_w1l; K = 512; P = 256; local = i - 36864; }
    else if (i < 110592) { src = w2; dh = g_w2h; dl = g_w2l; K = 256; P = 128; local = i - 102400; }
    else if (i < 217088) { src = t0; dh = g_t0h; dl = g_t0l; K = 415; P = 208; local = i - 110592; }
    else                 { src = t1; dh = g_t1h; dl = g_t1l; K = 512; P = 256; local = i - 217088; }
    int row = local / P, p = local - row * P, k = 2 * p;
    float v0 = (k     < K) ? src[(size_t)row * K + k]     : 0.f;
    float v1 = (k + 1 < K) ? src[(size_t)row * K + k + 1] : 0.f;
    float h0 = bf16_round(v0), h1 = bf16_round(v1);
    dh[local] = pack_bf16x2(h0, h1);
    dl[local] = pack_bf16x2(v0 - h0, v1 - h1);
}

// ---------------------------------------------------------------------------
// Embedding gather -> split T rows in global. One thread per (bag, quad).
// Runs on the SIDE stream, overlapped with the bottom MLP.
// ---------------------------------------------------------------------------
__global__ __launch_bounds__(256)
void gather_emb(const int* __restrict__ lS_o,
                const int* __restrict__ lS_i,
                const float* __restrict__ emb)
{
    int gid = blockIdx.x * 256 + threadIdx.x;     // ((b*26+t)*16 + q)
    if (gid >= BATCH * NTAB * 16) return;
    int q  = gid & 15;
    int bt = gid >> 4;
    int t  = bt % NTAB;
    int b  = bt / NTAB;

    int beg = __ldg(lS_o + t * BATCH + b);
    int end = (b + 1 < BATCH) ? __ldg(lS_o + t * BATCH + b + 1) : BATCH;

    const float* tab = emb + (size_t)t * VOCAB * EMBD + q * 4;
    float4 a = make_float4(0.f, 0.f, 0.f, 0.f);
    for (int p = beg; p < end; p++) {
        int i = __ldg(lS_i + t * BATCH + p);
        float4 v = *reinterpret_cast<const float4*>(tab + (size_t)i * EMBD);
        a.x += v.x; a.y += v.y; a.z += v.z; a.w += v.w;
    }
    float hx = bf16_round(a.x), hy = bf16_round(a.y);
    float hz = bf16_round(a.z), hw = bf16_round(a.w);
    uint32_t* Th = g_Th + (size_t)bt * 32 + q * 2;
    uint32_t* Tl = g_Tl + (size_t)bt * 32 + q * 2;
    Th[0] = pack_bf16x2(hx, hy);
    Tl[0] = pack_bf16x2(a.x - hx, a.y - hy);
    Th[1] = pack_bf16x2(hz, hw);
    Tl[1] = pack_bf16x2(a.z - hz, a.w - hw);
}

// ---------------------------------------------------------------------------
// NT GEMM, pre-split inputs, STAGES-deep cp.async pipeline.
// OUT_MODE: 0 = split-pair output (Ch/Cl), 2 = fused final layer
// (stage z2 rows in smem, dot with fw, sigmoid -> Cf[row]; needs BN == N).
// ---------------------------------------------------------------------------
template<int BM, int BN, int WM_, int WN_, int OUT_MODE, int STAGES>
__global__ __launch_bounds__(256)
void gemm_nt_mma(const uint32_t* __restrict__ Ah, const uint32_t* __restrict__ Al,
                 const uint32_t* __restrict__ Wh, const uint32_t* __restrict__ Wl,
                 const float* __restrict__ bias,
                 uint32_t* __restrict__ Ch, uint32_t* __restrict__ Cl,
                 float* __restrict__ Cf,
                 const float* __restrict__ fw, const float* __restrict__ fb,
                 int Kp, int ldap, int ldwp, int ldc)
{
    constexpr int TM  = BM / WM_;
    constexpr int TN  = BN / WN_;
    constexpr int MT  = TM / 16;
    constexpr int NTT = TN / 8;
    constexpr int NT2 = NTT / 2;
    constexpr int STG  = BM * SROWG;
    constexpr int STGW = BN * SROWG;

    extern __shared__ __align__(16) uint32_t dyn[];
    uint32_t* sHA = dyn;
    uint32_t* sLA = sHA + STAGES * STG;
    uint32_t* sHW = sLA + STAGES * STG;
    uint32_t* sLW = sHW + STAGES * STGW;

    const int tid  = threadIdx.x;
    const int lane = tid & 31;
    const int wid  = tid >> 5;
    const int wm   = wid % WM_;
    const int wn   = wid / WM_;
    const int g    = lane >> 2;
    const int tg   = lane & 3;
    const int bm   = blockIdx.y * BM;
    const int bn   = blockIdx.x * BN;

    const int sub_r  = lane & 7;
    const int quad   = lane >> 3;
    const int lm_row = sub_r + (quad & 1) * 8;
    const int lm_col = (quad >> 1) * 4;

    float acc[MT][NTT][4];
    #pragma unroll
    for (int i = 0; i < MT; i++)
        #pragma unroll
        for (int j = 0; j < NTT; j++)
            #pragma unroll
            for (int q = 0; q < 4; q++) acc[i][j][q] = 0.f;

    const int ntiles = (Kp + 15) / 16;

    auto load_stage = [&](int t, int s) {
        uint32_t* dHA = sHA + s * STG;
        uint32_t* dLA = sLA + s * STG;
        uint32_t* dHW = sHW + s * STGW;
        uint32_t* dLW = sLW + s * STGW;
        for (int i = tid; i < BM * 4; i += 256) {
            int row = i >> 2, c = i & 3;
            int gp = t * 16 + c * 4;
            int avail = (ldap - gp) * 4;
            avail = avail < 0 ? 0 : (avail > 16 ? 16 : avail);
            int gpc = gp < ldap - 4 ? gp : ldap - 4;
            size_t goff = (size_t)(bm + row) * ldap + gpc;
            cp16(dHA + row * SROWG + c * 4, Ah + goff, avail);
            cp16(dLA + row * SROWG + c * 4, Al + goff, avail);
        }
        for (int i = tid; i < BN * 4; i += 256) {
            int row = i >> 2, c = i & 3;
            int gp = t * 16 + c * 4;
            int avail = (ldwp - gp) * 4;
            avail = avail < 0 ? 0 : (avail > 16 ? 16 : avail);
            int gpc = gp < ldwp - 4 ? gp : ldwp - 4;
            size_t goff = (size_t)(bn + row) * ldwp + gpc;
            cp16(dHW + row * SROWG + c * 4, Wh + goff, avail);
            cp16(dLW + row * SROWG + c * 4, Wl + goff, avail);
        }
        cp_commit();
    };

    #pragma unroll
    for (int s = 0; s < STAGES - 1; s++) {
        if (s < ntiles) load_stage(s, s); else cp_commit();
    }

    for (int t = 0; t < ntiles; t++) {
        cp_wait<STAGES - 2>();
        __syncthreads();
        {
            int nt_ = t + STAGES - 1;
            if (nt_ < ntiles) load_stage(nt_, nt_ % STAGES); else cp_commit();
        }

        const int s = t % STAGES;
        const uint32_t* bHA = sHA + s * STG;
        const uint32_t* bLA = sLA + s * STG;
        const uint32_t* bHW = sHW + s * STGW;
        const uint32_t* bLW = sLW + s * STGW;

        #pragma unroll
        for (int ks = 0; ks < 2; ks++) {
            const int cb = ks * 8;
            uint32_t ah[MT][4], al[MT][4], bh[NTT][2], bl[NTT][2];
            #pragma unroll
            for (int mt = 0; mt < MT; mt++) {
                int base = (wm * TM + mt * 16 + lm_row) * SROWG + cb + lm_col;
                ldm_x4(ah[mt], &bHA[base]);
                ldm_x4(al[mt], &bLA[base]);
            }
            #pragma unroll
            for (int n2 = 0; n2 < NT2; n2++) {
                int base = (wn * TN + n2 * 16 + lm_row) * SROWG + cb + lm_col;
                uint32_t q[4];
                ldm_x4(q, &bHW[base]);
                bh[2 * n2][0] = q[0]; bh[2 * n2 + 1][0] = q[1];
                bh[2 * n2][1] = q[2]; bh[2 * n2 + 1][1] = q[3];
                ldm_x4(q, &bLW[base]);
                bl[2 * n2][0] = q[0]; bl[2 * n2 + 1][0] = q[1];
                bl[2 * n2][1] = q[2]; bl[2 * n2 + 1][1] = q[3];
            }
            #pragma unroll
            for (int mt = 0; mt < MT; mt++)
                #pragma unroll
                for (int nt = 0; nt < NTT; nt++) {
                    mma_bf16(acc[mt][nt], ah[mt], bh[nt]);
                    mma_bf16(acc[mt][nt], ah[mt], bl[nt]);
                    mma_bf16(acc[mt][nt], al[mt], bh[nt]);
                }
        }
        __syncthreads();
    }

    if (OUT_MODE == 0) {
        #pragma unroll
        for (int mt = 0; mt < MT; mt++) {
            int r0 = bm + wm * TM + mt * 16 + g;
            #pragma unroll
            for (int nt = 0; nt < NTT; nt++) {
                int col = bn + wn * TN + nt * 8 + tg * 2;
                float bi0 = bias[col], bi1 = bias[col + 1];
                float v0 = fmaxf(acc[mt][nt][0] + bi0, 0.f);
                float v1 = fmaxf(acc[mt][nt][1] + bi1, 0.f);
                float v2 = fmaxf(acc[mt][nt][2] + bi0, 0.f);
                float v3 = fmaxf(acc[mt][nt][3] + bi1, 0.f);
                int pj = col >> 1;
                float h0 = bf16_round(v0), h1 = bf16_round(v1);
                Ch[(size_t)r0 * ldc + pj] = pack_bf16x2(h0, h1);
                Cl[(size_t)r0 * ldc + pj] = pack_bf16x2(v0 - h0, v1 - h1);
                float h2 = bf16_round(v2), h3 = bf16_round(v3);
                Ch[(size_t)(r0 + 8) * ldc + pj] = pack_bf16x2(h2, h3);
                Cl[(size_t)(r0 + 8) * ldc + pj] = pack_bf16x2(v2 - h2, v3 - h3);
            }
        }
    } else {
        // fused final: stage relu(z2) rows in smem, dot with fw, sigmoid.
        float* sZr = reinterpret_cast<float*>(dyn + STAGES * (2 * STG + 2 * STGW));
        #pragma unroll
        for (int mt = 0; mt < MT; mt++) {
            int rl = wm * TM + mt * 16 + g;
            #pragma unroll
            for (int nt = 0; nt < NTT; nt++) {
                int col = bn + wn * TN + nt * 8 + tg * 2;
                float bi0 = bias[col], bi1 = bias[col + 1];
                sZr[rl * 258 + col]           = fmaxf(acc[mt][nt][0] + bi0, 0.f);
                sZr[rl * 258 + col + 1]       = fmaxf(acc[mt][nt][1] + bi1, 0.f);
                sZr[(rl + 8) * 258 + col]     = fmaxf(acc[mt][nt][2] + bi0, 0.f);
                sZr[(rl + 8) * 258 + col + 1] = fmaxf(acc[mt][nt][3] + bi1, 0.f);
            }
        }
        __syncthreads();
        float fb0 = __ldg(fb);
        #pragma unroll
        for (int rr = 0; rr < BM / 8; rr++) {
            int r = wid * (BM / 8) + rr;
            float s = 0.f;
            #pragma unroll
            for (int k = lane; k < BN; k += 32) s = fmaf(sZr[r * 258 + k], __ldg(fw + k), s);
            #pragma unroll
            for (int o = 16; o; o >>= 1) s += __shfl_xor_sync(0xFFFFFFFFu, s, o);
            if (lane == 0) Cf[bm + r] = 1.f / (1.f + expf(-(s + fb0)));
        }
    }
}

// ---------------------------------------------------------------------------
// Interaction (gather already done): load split T rows, Z = T T^T, write R.
// ---------------------------------------------------------------------------
__global__ __launch_bounds__(256)
void interact()
{
    __shared__ uint32_t sH[32 * SROW];
    __shared__ uint32_t sL[32 * SROW];
    __shared__ float    sZ[NPAIR];

    const int b    = blockIdx.x;
    const int tid  = threadIdx.x;
    const int lane = tid & 31;
    const int wid  = tid >> 5;

    if (tid < 32) {
        sH[tid] = g_x3h[(size_t)b * 32 + tid];
        sL[tid] = g_x3l[(size_t)b * 32 + tid];
    }
    for (int i = tid; i < NTAB * 32; i += 256) {
        int t = i >> 5, pj = i & 31;
        sH[(t + 1) * SROW + pj] = g_Th[((size_t)b * NTAB + t) * 32 + pj];
        sL[(t + 1) * SROW + pj] = g_Tl[((size_t)b * NTAB + t) * 32 + pj];
    }
    __syncthreads();

    const int g  = lane >> 2;
    const int tg = lane & 3;
    const int wm = wid & 1;
    const int wn = wid >> 1;

    float acc[4] = {0.f, 0.f, 0.f, 0.f};
    const int r0 = wm * 16 + g;
    const int r1 = r0 + 8;
    const int nb = wn * 8 + g;

    #pragma unroll
    for (int ks = 0; ks < 4; ks++) {
        int kp = ks * 8 + tg;
        uint32_t ah[4], al[4], bh[2], bl[2];
        ah[0] = sH[r0 * SROW + kp];     al[0] = sL[r0 * SROW + kp];
        ah[1] = sH[r1 * SROW + kp];     al[1] = sL[r1 * SROW + kp];
        ah[2] = sH[r0 * SROW + kp + 4]; al[2] = sL[r0 * SROW + kp + 4];
        ah[3] = sH[r1 * SROW + kp + 4]; al[3] = sL[r1 * SROW + kp + 4];
        bh[0] = sH[nb * SROW + kp];     bl[0] = sL[nb * SROW + kp];
        bh[1] = sH[nb * SROW + kp + 4]; bl[1] = sL[nb * SROW + kp + 4];
        mma_bf16(acc, ah, bh);
        mma_bf16(acc, ah, bl);
        mma_bf16(acc, al, bh);
    }

    {
        int row = wm * 16 + g;
        int col = wn * 8 + tg * 2;
        if (row < NT1) {
            int base = row * (row - 1) / 2;
            if (col     < row) sZ[base + col]     = acc[0];
            if (col + 1 < row) sZ[base + col + 1] = acc[1];
        }
        int row2 = row + 8;
        if (row2 < NT1) {
            int base = row2 * (row2 - 1) / 2;
            if (col     < row2) sZ[base + col]     = acc[2];
            if (col + 1 < row2) sZ[base + col + 1] = acc[3];
        }
    }
    __syncthreads();

    uint32_t* Rh = g_Rh + (size_t)b * RP;
    uint32_t* Rl = g_Rl + (size_t)b * RP;
    for (int pj = tid; pj < RP; pj += 256) {
        if (pj < 32) {
            Rh[pj] = g_x3h[(size_t)b * 32 + pj];
            Rl[pj] = g_x3l[(size_t)b * 32 + pj];
        } else {
            int e0 = 2 * pj - 64;
            float v0 = sZ[e0];
            float v1 = (e0 + 1 < NPAIR) ? sZ[e0 + 1] : 0.f;
            float h0 = bf16_round(v0), h1 = bf16_round(v1);
            Rh[pj] = pack_bf16x2(h0, h1);
            Rl[pj] = pack_bf16x2(v0 - h0, v1 - h1);
        }
    }
}

// ---------------------------------------------------------------------------
static inline int smem_bytes(int BM, int BN, int stages, bool fuse)
{
    int b = stages * (2 * BM + 2 * BN) * SROWG * 4;
    if (fuse) b += BM * 258 * 4;
    return b;
}

extern "C" void kernel_launch(void* const* d_in, const int* in_sizes, int n_in,
                              void* d_out, int out_size)
{
    const float* dense_x = (const float*)d_in[0];
    const int*   lS_o    = (const int*)  d_in[1];
    const int*   lS_i    = (const int*)  d_in[2];
    const float* emb     = (const float*)d_in[3];
    const float* bw0     = (const float*)d_in[4];
    const float* bb0     = (const float*)d_in[5];
    const float* bw1     = (const float*)d_in[6];
    const float* bb1     = (const float*)d_in[7];
    const float* bw2     = (const float*)d_in[8];
    const float* bb2     = (const float*)d_in[9];
    const float* tw0     = (const float*)d_in[10];
    const float* tb0     = (const float*)d_in[11];
    const float* tw1     = (const float*)d_in[12];
    const float* tb1     = (const float*)d_in[13];
    const float* tw2     = (const float*)d_in[14];
    const float* tb2     = (const float*)d_in[15];
    float* out = (float*)d_out;

    uint32_t *dxh, *dxl, *w0h, *w0l, *w1h, *w1l, *w2h, *w2l, *t0h, *t0l, *t1h, *t1l;
    uint32_t *x1h, *x1l, *x2h, *x2l, *x3h, *x3l, *Rh, *Rl, *z1h, *z1l;
    cudaGetSymbolAddress((void**)&dxh, g_dxh); cudaGetSymbolAddress((void**)&dxl, g_dxl);
    cudaGetSymbolAddress((void**)&w0h, g_w0h); cudaGetSymbolAddress((void**)&w0l, g_w0l);
    cudaGetSymbolAddress((void**)&w1h, g_w1h); cudaGetSymbolAddress((void**)&w1l, g_w1l);
    cudaGetSymbolAddress((void**)&w2h, g_w2h); cudaGetSymbolAddress((void**)&w2l, g_w2l);
    cudaGetSymbolAddress((void**)&t0h, g_t0h); cudaGetSymbolAddress((void**)&t0l, g_t0l);
    cudaGetSymbolAddress((void**)&t1h, g_t1h); cudaGetSymbolAddress((void**)&t1l, g_t1l);
    cudaGetSymbolAddress((void**)&x1h, g_x1h); cudaGetSymbolAddress((void**)&x1l, g_x1l);
    cudaGetSymbolAddress((void**)&x2h, g_x2h); cudaGetSymbolAddress((void**)&x2l, g_x2l);
    cudaGetSymbolAddress((void**)&x3h, g_x3h); cudaGetSymbolAddress((void**)&x3l, g_x3l);
    cudaGetSymbolAddress((void**)&Rh,  g_Rh);  cudaGetSymbolAddress((void**)&Rl,  g_Rl);
    cudaGetSymbolAddress((void**)&z1h, g_z1h); cudaGetSymbolAddress((void**)&z1l, g_z1l);

    cudaFuncSetAttribute(gemm_nt_mma<128, 128, 2, 4, 0, 2>,
                         cudaFuncAttributeMaxDynamicSharedMemorySize, smem_bytes(128, 128, 2, false));
    cudaFuncSetAttribute(gemm_nt_mma<128, 128, 2, 4, 0, 4>,
                         cudaFuncAttributeMaxDynamicSharedMemorySize, smem_bytes(128, 128, 4, false));
    cudaFuncSetAttribute(gemm_nt_mma<64, 128, 2, 4, 0, 4>,
                         cudaFuncAttributeMaxDynamicSharedMemorySize, smem_bytes(64, 128, 4, false));
    cudaFuncSetAttribute(gemm_nt_mma<32, 64, 2, 4, 0, 4>,
                         cudaFuncAttributeMaxDynamicSharedMemorySize, smem_bytes(32, 64, 4, false));
    cudaFuncSetAttribute(gemm_nt_mma<32, 256, 2, 4, 2, 3>,
                         cudaFuncAttributeMaxDynamicSharedMemorySize, smem_bytes(32, 256, 3, true));

    // fork/join machinery (created once; creation happens outside graph replay)
    static cudaStream_t s_side = nullptr;
    static cudaEvent_t ev_fork = nullptr, ev_join = nullptr;
    if (s_side == nullptr) {
        cudaStreamCreateWithFlags(&s_side, cudaStreamNonBlocking);
        cudaEventCreateWithFlags(&ev_fork, cudaEventDisableTiming);
        cudaEventCreateWithFlags(&ev_join, cudaEventDisableTiming);
    }

    // ---- fork: embedding gather runs concurrently with split + bottom MLP
    cudaEventRecord(ev_fork, 0);
    cudaStreamWaitEvent(s_side, ev_fork, 0);
    gather_emb<<<(BATCH * NTAB * 16 + 255) / 256, 256, 0, s_side>>>(lS_o, lS_i, emb);
    cudaEventRecord(ev_join, s_side);

    // ---- main stream: split + bottom MLP
    split_all<<<(282624 + 255) / 256, 256>>>(dense_x, bw0, bw1, bw2, tw0, tw1);
    gemm_nt_mma<128, 128, 2, 4, 0, 2><<<dim3(4, 32), 256, smem_bytes(128, 128, 2, false)>>>(
        dxh, dxl, w0h, w0l, bb0, x1h, x1l, nullptr, nullptr, nullptr, 7, 8, 8, 256);
    gemm_nt_mma<64, 128, 2, 4, 0, 4><<<dim3(2, 64), 256, smem_bytes(64, 128, 4, false)>>>(
        x1h, x1l, w1h, w1l, bb1, x2h, x2l, nullptr, nullptr, nullptr, 256, 256, 256, 128);
    gemm_nt_mma<32, 64, 2, 4, 0, 4><<<dim3(1, 128), 256, smem_bytes(32, 64, 4, false)>>>(
        x2h, x2l, w2h, w2l, bb2, x3h, x3l, nullptr, nullptr, nullptr, 128, 128, 128, 32);

    // ---- join: interaction needs gather results + x3
    cudaStreamWaitEvent(0, ev_join, 0);
    interact<<<BATCH, 256>>>();

    // ---- top MLP (final layer fused into T1)
    gemm_nt_mma<128, 128, 2, 4, 0, 4><<<dim3(4, 32), 256, smem_bytes(128, 128, 4, false)>>>(
        Rh, Rl, t0h, t0l, tb0, z1h, z1l, nullptr, nullptr, nullptr, RP, RP, RP, 256);
    gemm_nt_mma<32, 256, 2, 4, 2, 3><<<dim3(1, 128), 256, smem_bytes(32, 256, 3, true)>>>(
        z1h, z1l, t1h, t1l, tb1, nullptr, nullptr, out, tw2, tb2, 256, 256, 256, 0);
}

// round 14
// speedup vs baseline: 1.1344x; 1.1344x over previous
#include <cuda_runtime.h>
#include <cuda_bf16.h>
#include <math.h>
#include <stdint.h>

#define BATCH 4096
#define NTAB 26
#define VOCAB 100000
#define EMBD 64
#define NT1 27
#define NPAIR 351
#define RDIM 415
#define RP 208            // pairs per R row
#define SROW 36           // interact smem row stride (u32)
#define SROWG 20          // gemm smem row stride (u32): 16 pairs + 4 pad

// ---- pre-split weight / input buffers (hi/lo bf16x2 pairs) ----
__device__ uint32_t g_dxh[BATCH * 8],  g_dxl[BATCH * 8];
__device__ uint32_t g_w0h[512 * 8],    g_w0l[512 * 8];
__device__ uint32_t g_w1h[256 * 256],  g_w1l[256 * 256];
__device__ uint32_t g_w2h[64 * 128],   g_w2l[64 * 128];
__device__ uint32_t g_t0h[512 * 208],  g_t0l[512 * 208];
__device__ uint32_t g_t1h[256 * 256],  g_t1l[256 * 256];
// ---- split activations ----
__device__ uint32_t g_x1h[BATCH * 256], g_x1l[BATCH * 256];
__device__ uint32_t g_x2h[BATCH * 128], g_x2l[BATCH * 128];
__device__ uint32_t g_x3h[BATCH * 32],  g_x3l[BATCH * 32];
__device__ uint32_t g_Rh [BATCH * RP],  g_Rl [BATCH * RP];
__device__ uint32_t g_z1h[BATCH * 256], g_z1l[BATCH * 256];

__device__ __forceinline__ uint32_t pack_bf16x2(float lo, float hi)
{
    __nv_bfloat162 p = __floats2bfloat162_rn(lo, hi);
    return *reinterpret_cast<uint32_t*>(&p);
}
__device__ __forceinline__ float bf16_round(float v)
{
    return __bfloat162float(__float2bfloat16(v));
}
__device__ __forceinline__ void mma_bf16(float* c, const uint32_t* a, const uint32_t* b)
{
    asm volatile(
        "mma.sync.aligned.m16n8k16.row.col.f32.bf16.bf16.f32 "
        "{%0,%1,%2,%3}, {%4,%5,%6,%7}, {%8,%9}, {%0,%1,%2,%3};"
        : "+f"(c[0]), "+f"(c[1]), "+f"(c[2]), "+f"(c[3])
        : "r"(a[0]), "r"(a[1]), "r"(a[2]), "r"(a[3]), "r"(b[0]), "r"(b[1]));
}
__device__ __forceinline__ void ldm_x4(uint32_t* r, const uint32_t* p)
{
    uint32_t a = (uint32_t)__cvta_generic_to_shared(p);
    asm volatile("ldmatrix.sync.aligned.m8n8.x4.shared.b16 {%0,%1,%2,%3}, [%4];"
        : "=r"(r[0]), "=r"(r[1]), "=r"(r[2]), "=r"(r[3]) : "r"(a));
}
__device__ __forceinline__ void cp16(const uint32_t* dst, const uint32_t* src, int bytes)
{
    uint32_t d = (uint32_t)__cvta_generic_to_shared(dst);
    asm volatile("cp.async.cg.shared.global [%0], [%1], 16, %2;\n"
                 :: "r"(d), "l"(src), "r"(bytes));
}
__device__ __forceinline__ void cp_commit() { asm volatile("cp.async.commit_group;\n"); }
template<int N>
__device__ __forceinline__ void cp_wait() { asm volatile("cp.async.wait_group %0;\n" :: "n"(N)); }

// ---------------------------------------------------------------------------
// Split dense_x + 5 weight matrices into bf16 hi/lo pair arrays.
// ---------------------------------------------------------------------------
__global__ __launch_bounds__(256)
void split_all(const float* __restrict__ dx, const float* __restrict__ w0,
               const float* __restrict__ w1, const float* __restrict__ w2,
               const float* __restrict__ t0, const float* __restrict__ t1)
{
    int i = blockIdx.x * 256 + threadIdx.x;
    if (i >= 282624) return;
    const float* src; uint32_t *dh, *dl; int K, P, local;
    if (i < 32768)       { src = dx; dh = g_dxh; dl = g_dxl; K = 13;  P = 8;   local = i; }
    else if (i < 36864)  { src = w0; dh = g_w0h; dl = g_w0l; K = 13;  P = 8;   local = i - 32768; }
    else if (i < 102400) { src = w1; dh = g_w1h; dl = g_w1l; K = 512; P = 256; local = i - 36864; }
    else if (i < 110592) { src = w2; dh = g_w2h; dl = g_w2l; K = 256; P = 128; local = i - 102400; }
    else if (i < 217088) { src = t0; dh = g_t0h; dl = g_t0l; K = 415; P = 208; local = i - 110592; }
    else                 { src = t1; dh = g_t1h; dl = g_t1l; K = 512; P = 256; local = i - 217088; }
    int row = local / P, p = local - row * P, k = 2 * p;
    float v0 = (k     < K) ? src[(size_t)row * K + k]     : 0.f;
    float v1 = (k + 1 < K) ? src[(size_t)row * K + k + 1] : 0.f;
    float h0 = bf16_round(v0), h1 = bf16_round(v1);
    dh[local] = pack_bf16x2(h0, h1);
    dl[local] = pack_bf16x2(v0 - h0, v1 - h1);
}

// ---------------------------------------------------------------------------
// NT GEMM, pre-split inputs, STAGES-deep cp.async pipeline.
// OUT_MODE: 0 = split-pair output (Ch/Cl); 2 = fused final layer
// (stage relu(z) rows in smem, dot with fw, sigmoid -> Cf[row]; needs BN==N).
// ---------------------------------------------------------------------------
template<int BM, int BN, int WM_, int WN_, int OUT_MODE, int STAGES>
__global__ __launch_bounds__(256)
void gemm_nt_mma(const uint32_t* __restrict__ Ah, const uint32_t* __restrict__ Al,
                 const uint32_t* __restrict__ Wh, const uint32_t* __restrict__ Wl,
                 const float* __restrict__ bias,
                 uint32_t* __restrict__ Ch, uint32_t* __restrict__ Cl,
                 float* __restrict__ Cf,
                 const float* __restrict__ fw, const float* __restrict__ fb,
                 int Kp, int ldap, int ldwp, int ldc)
{
    constexpr int TM  = BM / WM_;
    constexpr int TN  = BN / WN_;
    constexpr int MT  = TM / 16;
    constexpr int NTT = TN / 8;
    constexpr int NT2 = NTT / 2;
    constexpr int STG  = BM * SROWG;
    constexpr int STGW = BN * SROWG;

    extern __shared__ __align__(16) uint32_t dyn[];
    uint32_t* sHA = dyn;
    uint32_t* sLA = sHA + STAGES * STG;
    uint32_t* sHW = sLA + STAGES * STG;
    uint32_t* sLW = sHW + STAGES * STGW;

    const int tid  = threadIdx.x;
    const int lane = tid & 31;
    const int wid  = tid >> 5;
    const int wm   = wid % WM_;
    const int wn   = wid / WM_;
    const int g    = lane >> 2;
    const int tg   = lane & 3;
    const int bm   = blockIdx.y * BM;
    const int bn   = blockIdx.x * BN;

    const int sub_r  = lane & 7;
    const int quad   = lane >> 3;
    const int lm_row = sub_r + (quad & 1) * 8;
    const int lm_col = (quad >> 1) * 4;

    float acc[MT][NTT][4];
    #pragma unroll
    for (int i = 0; i < MT; i++)
        #pragma unroll
        for (int j = 0; j < NTT; j++)
            #pragma unroll
            for (int q = 0; q < 4; q++) acc[i][j][q] = 0.f;

    const int ntiles = (Kp + 15) / 16;

    auto load_stage = [&](int t, int s) {
        uint32_t* dHA = sHA + s * STG;
        uint32_t* dLA = sLA + s * STG;
        uint32_t* dHW = sHW + s * STGW;
        uint32_t* dLW = sLW + s * STGW;
        for (int i = tid; i < BM * 4; i += 256) {
            int row = i >> 2, c = i & 3;
            int gp = t * 16 + c * 4;
            int avail = (ldap - gp) * 4;
            avail = avail < 0 ? 0 : (avail > 16 ? 16 : avail);
            int gpc = gp < ldap - 4 ? gp : ldap - 4;
            size_t goff = (size_t)(bm + row) * ldap + gpc;
            cp16(dHA + row * SROWG + c * 4, Ah + goff, avail);
            cp16(dLA + row * SROWG + c * 4, Al + goff, avail);
        }
        for (int i = tid; i < BN * 4; i += 256) {
            int row = i >> 2, c = i & 3;
            int gp = t * 16 + c * 4;
            int avail = (ldwp - gp) * 4;
            avail = avail < 0 ? 0 : (avail > 16 ? 16 : avail);
            int gpc = gp < ldwp - 4 ? gp : ldwp - 4;
            size_t goff = (size_t)(bn + row) * ldwp + gpc;
            cp16(dHW + row * SROWG + c * 4, Wh + goff, avail);
            cp16(dLW + row * SROWG + c * 4, Wl + goff, avail);
        }
        cp_commit();
    };

    #pragma unroll
    for (int s = 0; s < STAGES - 1; s++) {
        if (s < ntiles) load_stage(s, s); else cp_commit();
    }

    for (int t = 0; t < ntiles; t++) {
        cp_wait<STAGES - 2>();
        __syncthreads();
        {
            int nt_ = t + STAGES - 1;
            if (nt_ < ntiles) load_stage(nt_, nt_ % STAGES); else cp_commit();
        }

        const int s = t % STAGES;
        const uint32_t* bHA = sHA + s * STG;
        const uint32_t* bLA = sLA + s * STG;
        const uint32_t* bHW = sHW + s * STGW;
        const uint32_t* bLW = sLW + s * STGW;

        #pragma unroll
        for (int ks = 0; ks < 2; ks++) {
            const int cb = ks * 8;
            uint32_t ah[MT][4], al[MT][4], bh[NTT][2], bl[NTT][2];
            #pragma unroll
            for (int mt = 0; mt < MT; mt++) {
                int base = (wm * TM + mt * 16 + lm_row) * SROWG + cb + lm_col;
                ldm_x4(ah[mt], &bHA[base]);
                ldm_x4(al[mt], &bLA[base]);
            }
            #pragma unroll
            for (int n2 = 0; n2 < NT2; n2++) {
                int base = (wn * TN + n2 * 16 + lm_row) * SROWG + cb + lm_col;
                uint32_t q[4];
                ldm_x4(q, &bHW[base]);
                bh[2 * n2][0] = q[0]; bh[2 * n2 + 1][0] = q[1];
                bh[2 * n2][1] = q[2]; bh[2 * n2 + 1][1] = q[3];
                ldm_x4(q, &bLW[base]);
                bl[2 * n2][0] = q[0]; bl[2 * n2 + 1][0] = q[1];
                bl[2 * n2][1] = q[2]; bl[2 * n2 + 1][1] = q[3];
            }
            #pragma unroll
            for (int mt = 0; mt < MT; mt++)
                #pragma unroll
                for (int nt = 0; nt < NTT; nt++) {
                    mma_bf16(acc[mt][nt], ah[mt], bh[nt]);
                    mma_bf16(acc[mt][nt], ah[mt], bl[nt]);
                    mma_bf16(acc[mt][nt], al[mt], bh[nt]);
                }
        }
        __syncthreads();
    }

    if (OUT_MODE == 0) {
        #pragma unroll
        for (int mt = 0; mt < MT; mt++) {
            int r0 = bm + wm * TM + mt * 16 + g;
            #pragma unroll
            for (int nt = 0; nt < NTT; nt++) {
                int col = bn + wn * TN + nt * 8 + tg * 2;
                float bi0 = bias[col], bi1 = bias[col + 1];
                float v0 = fmaxf(acc[mt][nt][0] + bi0, 0.f);
                float v1 = fmaxf(acc[mt][nt][1] + bi1, 0.f);
                float v2 = fmaxf(acc[mt][nt][2] + bi0, 0.f);
                float v3 = fmaxf(acc[mt][nt][3] + bi1, 0.f);
                int pj = col >> 1;
                float h0 = bf16_round(v0), h1 = bf16_round(v1);
                Ch[(size_t)r0 * ldc + pj] = pack_bf16x2(h0, h1);
                Cl[(size_t)r0 * ldc + pj] = pack_bf16x2(v0 - h0, v1 - h1);
                float h2 = bf16_round(v2), h3 = bf16_round(v3);
                Ch[(size_t)(r0 + 8) * ldc + pj] = pack_bf16x2(h2, h3);
                Cl[(size_t)(r0 + 8) * ldc + pj] = pack_bf16x2(v2 - h2, v3 - h3);
            }
        }
    } else {
        // fused final layer: stage relu(z) rows in smem, dot with fw, sigmoid.
        float* sZr = reinterpret_cast<float*>(dyn + STAGES * (2 * STG + 2 * STGW));
        #pragma unroll
        for (int mt = 0; mt < MT; mt++) {
            int rl = wm * TM + mt * 16 + g;
            #pragma unroll
            for (int nt = 0; nt < NTT; nt++) {
                int col = bn + wn * TN + nt * 8 + tg * 2;
                float bi0 = bias[col], bi1 = bias[col + 1];
                sZr[rl * 258 + col]           = fmaxf(acc[mt][nt][0] + bi0, 0.f);
                sZr[rl * 258 + col + 1]       = fmaxf(acc[mt][nt][1] + bi1, 0.f);
                sZr[(rl + 8) * 258 + col]     = fmaxf(acc[mt][nt][2] + bi0, 0.f);
                sZr[(rl + 8) * 258 + col + 1] = fmaxf(acc[mt][nt][3] + bi1, 0.f);
            }
        }
        __syncthreads();
        float fb0 = __ldg(fb);
        #pragma unroll
        for (int rr = 0; rr < BM / 8; rr++) {
            int r = wid * (BM / 8) + rr;
            float s = 0.f;
            #pragma unroll
            for (int k = lane; k < BN; k += 32) s = fmaf(sZr[r * 258 + k], __ldg(fw + k), s);
            #pragma unroll
            for (int o = 16; o; o >>= 1) s += __shfl_xor_sync(0xFFFFFFFFu, s, o);
            if (lane == 0) Cf[bm + r] = 1.f / (1.f + expf(-(s + fb0)));
        }
    }
}

// ---------------------------------------------------------------------------
// Fused embedding-gather + interaction (split-pair I/O). Sequential schedule.
// ---------------------------------------------------------------------------
__global__ __launch_bounds__(256)
void gather_interact(const int* __restrict__ lS_o,
                     const int* __restrict__ lS_i,
                     const float* __restrict__ emb)
{
    __shared__ uint32_t sH[32 * SROW];
    __shared__ uint32_t sL[32 * SROW];
    __shared__ float    sZ[NPAIR];
    __shared__ int s_beg[NTAB];
    __shared__ int s_len[NTAB];
    __shared__ int s_idx[NTAB];

    const int b    = blockIdx.x;
    const int tid  = threadIdx.x;
    const int lane = tid & 31;
    const int wid  = tid >> 5;

    if (tid < NTAB) {
        int beg = lS_o[tid * BATCH + b];
        int end = (b + 1 < BATCH) ? lS_o[tid * BATCH + b + 1] : BATCH;
        s_beg[tid] = beg;
        s_len[tid] = end - beg;
        s_idx[tid] = (end - beg == 1) ? __ldg(lS_i + tid * BATCH + beg) : -1;
    }
    if (tid < 32) {
        sH[tid] = g_x3h[(size_t)b * 32 + tid];
        sL[tid] = g_x3l[(size_t)b * 32 + tid];
    }
    __syncthreads();

    {
        const int t0 = tid >> 4;
        const int q  = tid & 15;
        const int t1 = t0 + 16;
        const bool has1 = (t1 < NTAB);

        const float* tab0 = emb + (size_t)t0 * VOCAB * EMBD + q * 4;
        const float* tab1 = emb + (size_t)t1 * VOCAB * EMBD + q * 4;

        float4 a0 = make_float4(0.f, 0.f, 0.f, 0.f);
        float4 a1 = make_float4(0.f, 0.f, 0.f, 0.f);

        int i0f = s_idx[t0];
        int i1f = has1 ? s_idx[t1] : 0;

        if (i0f >= 0 && i1f >= 0) {
            if (has1) {
                float4 v0 = *reinterpret_cast<const float4*>(tab0 + (size_t)i0f * EMBD);
                float4 v1 = *reinterpret_cast<const float4*>(tab1 + (size_t)i1f * EMBD);
                a0 = v0; a1 = v1;
            } else {
                a0 = *reinterpret_cast<const float4*>(tab0 + (size_t)i0f * EMBD);
            }
        } else {
            int p0 = s_beg[t0], e0 = p0 + s_len[t0];
            int p1 = has1 ? s_beg[t1] : 0;
            int e1 = has1 ? (p1 + s_len[t1]) : 0;
            while (p0 < e0 || p1 < e1) {
                int i0 = (p0 < e0) ? __ldg(lS_i + t0 * BATCH + p0) : -1;
                int i1 = (p1 < e1) ? __ldg(lS_i + t1 * BATCH + p1) : -1;
                if (i0 >= 0) {
                    float4 v = *reinterpret_cast<const float4*>(tab0 + (size_t)i0 * EMBD);
                    a0.x += v.x; a0.y += v.y; a0.z += v.z; a0.w += v.w;
                    p0++;
                }
                if (i1 >= 0) {
                    float4 v = *reinterpret_cast<const float4*>(tab1 + (size_t)i1 * EMBD);
                    a1.x += v.x; a1.y += v.y; a1.z += v.z; a1.w += v.w;
                    p1++;
                }
            }
        }

        {
            float hx = bf16_round(a0.x), hy = bf16_round(a0.y);
            float hz = bf16_round(a0.z), hw = bf16_round(a0.w);
            int base = (t0 + 1) * SROW + q * 2;
            sH[base]     = pack_bf16x2(hx, hy);
            sL[base]     = pack_bf16x2(a0.x - hx, a0.y - hy);
            sH[base + 1] = pack_bf16x2(hz, hw);
            sL[base + 1] = pack_bf16x2(a0.z - hz, a0.w - hw);
        }
        if (has1) {
            float hx = bf16_round(a1.x), hy = bf16_round(a1.y);
            float hz = bf16_round(a1.z), hw = bf16_round(a1.w);
            int base = (t1 + 1) * SROW + q * 2;
            sH[base]     = pack_bf16x2(hx, hy);
            sL[base]     = pack_bf16x2(a1.x - hx, a1.y - hy);
            sH[base + 1] = pack_bf16x2(hz, hw);
            sL[base + 1] = pack_bf16x2(a1.z - hz, a1.w - hw);
        }
    }
    __syncthreads();

    const int g  = lane >> 2;
    const int tg = lane & 3;
    const int wm = wid & 1;
    const int wn = wid >> 1;

    float acc[4] = {0.f, 0.f, 0.f, 0.f};
    const int r0 = wm * 16 + g;
    const int r1 = r0 + 8;
    const int nb = wn * 8 + g;

    #pragma unroll
    for (int ks = 0; ks < 4; ks++) {
        int kp = ks * 8 + tg;
        uint32_t ah[4], al[4], bh[2], bl[2];
        ah[0] = sH[r0 * SROW + kp];     al[0] = sL[r0 * SROW + kp];
        ah[1] = sH[r1 * SROW + kp];     al[1] = sL[r1 * SROW + kp];
        ah[2] = sH[r0 * SROW + kp + 4]; al[2] = sL[r0 * SROW + kp + 4];
        ah[3] = sH[r1 * SROW + kp + 4]; al[3] = sL[r1 * SROW + kp + 4];
        bh[0] = sH[nb * SROW + kp];     bl[0] = sL[nb * SROW + kp];
        bh[1] = sH[nb * SROW + kp + 4]; bl[1] = sL[nb * SROW + kp + 4];
        mma_bf16(acc, ah, bh);
        mma_bf16(acc, ah, bl);
        mma_bf16(acc, al, bh);
    }

    {
        int row = wm * 16 + g;
        int col = wn * 8 + tg * 2;
        if (row < NT1) {
            int base = row * (row - 1) / 2;
            if (col     < row) sZ[base + col]     = acc[0];
            if (col + 1 < row) sZ[base + col + 1] = acc[1];
        }
        int row2 = row + 8;
        if (row2 < NT1) {
            int base = row2 * (row2 - 1) / 2;
            if (col     < row2) sZ[base + col]     = acc[2];
            if (col + 1 < row2) sZ[base + col + 1] = acc[3];
        }
    }
    __syncthreads();

    uint32_t* Rh = g_Rh + (size_t)b * RP;
    uint32_t* Rl = g_Rl + (size_t)b * RP;
    for (int pj = tid; pj < RP; pj += 256) {
        if (pj < 32) {
            Rh[pj] = g_x3h[(size_t)b * 32 + pj];
            Rl[pj] = g_x3l[(size_t)b * 32 + pj];
        } else {
            int e0 = 2 * pj - 64;
            float v0 = sZ[e0];
            float v1 = (e0 + 1 < NPAIR) ? sZ[e0 + 1] : 0.f;
            float h0 = bf16_round(v0), h1 = bf16_round(v1);
            Rh[pj] = pack_bf16x2(h0, h1);
            Rl[pj] = pack_bf16x2(v0 - h0, v1 - h1);
        }
    }
}

// ---------------------------------------------------------------------------
static inline int smem_bytes(int BM, int BN, int stages, bool fuse)
{
    int b = stages * (2 * BM + 2 * BN) * SROWG * 4;
    if (fuse) b += BM * 258 * 4;
    return b;
}

extern "C" void kernel_launch(void* const* d_in, const int* in_sizes, int n_in,
                              void* d_out, int out_size)
{
    const float* dense_x = (const float*)d_in[0];
    const int*   lS_o    = (const int*)  d_in[1];
    const int*   lS_i    = (const int*)  d_in[2];
    const float* emb     = (const float*)d_in[3];
    const float* bw0     = (const float*)d_in[4];
    const float* bb0     = (const float*)d_in[5];
    const float* bw1     = (const float*)d_in[6];
    const float* bb1     = (const float*)d_in[7];
    const float* bw2     = (const float*)d_in[8];
    const float* bb2     = (const float*)d_in[9];
    const float* tw0     = (const float*)d_in[10];
    const float* tb0     = (const float*)d_in[11];
    const float* tw1     = (const float*)d_in[12];
    const float* tb1     = (const float*)d_in[13];
    const float* tw2     = (const float*)d_in[14];
    const float* tb2     = (const float*)d_in[15];
    float* out = (float*)d_out;

    uint32_t *dxh, *dxl, *w0h, *w0l, *w1h, *w1l, *w2h, *w2l, *t0h, *t0l, *t1h, *t1l;
    uint32_t *x1h, *x1l, *x2h, *x2l, *x3h, *x3l, *Rh, *Rl, *z1h, *z1l;
    cudaGetSymbolAddress((void**)&dxh, g_dxh); cudaGetSymbolAddress((void**)&dxl, g_dxl);
    cudaGetSymbolAddress((void**)&w0h, g_w0h); cudaGetSymbolAddress((void**)&w0l, g_w0l);
    cudaGetSymbolAddress((void**)&w1h, g_w1h); cudaGetSymbolAddress((void**)&w1l, g_w1l);
    cudaGetSymbolAddress((void**)&w2h, g_w2h); cudaGetSymbolAddress((void**)&w2l, g_w2l);
    cudaGetSymbolAddress((void**)&t0h, g_t0h); cudaGetSymbolAddress((void**)&t0l, g_t0l);
    cudaGetSymbolAddress((void**)&t1h, g_t1h); cudaGetSymbolAddress((void**)&t1l, g_t1l);
    cudaGetSymbolAddress((void**)&x1h, g_x1h); cudaGetSymbolAddress((void**)&x1l, g_x1l);
    cudaGetSymbolAddress((void**)&x2h, g_x2h); cudaGetSymbolAddress((void**)&x2l, g_x2l);
    cudaGetSymbolAddress((void**)&x3h, g_x3h); cudaGetSymbolAddress((void**)&x3l, g_x3l);
    cudaGetSymbolAddress((void**)&Rh,  g_Rh);  cudaGetSymbolAddress((void**)&Rl,  g_Rl);
    cudaGetSymbolAddress((void**)&z1h, g_z1h); cudaGetSymbolAddress((void**)&z1l, g_z1l);

    cudaFuncSetAttribute(gemm_nt_mma<128, 128, 2, 4, 0, 2>,
                         cudaFuncAttributeMaxDynamicSharedMemorySize, smem_bytes(128, 128, 2, false));
    cudaFuncSetAttribute(gemm_nt_mma<128, 128, 2, 4, 0, 4>,
                         cudaFuncAttributeMaxDynamicSharedMemorySize, smem_bytes(128, 128, 4, false));
    cudaFuncSetAttribute(gemm_nt_mma<64, 128, 2, 4, 0, 4>,
                         cudaFuncAttributeMaxDynamicSharedMemorySize, smem_bytes(64, 128, 4, false));
    cudaFuncSetAttribute(gemm_nt_mma<32, 64, 2, 4, 0, 4>,
                         cudaFuncAttributeMaxDynamicSharedMemorySize, smem_bytes(32, 64, 4, false));
    cudaFuncSetAttribute(gemm_nt_mma<32, 256, 2, 4, 2, 3>,
                         cudaFuncAttributeMaxDynamicSharedMemorySize, smem_bytes(32, 256, 3, true));

    // 0) split inputs/weights
    split_all<<<(282624 + 255) / 256, 256>>>(dense_x, bw0, bw1, bw2, tw0, tw1);

    // 1) bottom MLP
    gemm_nt_mma<128, 128, 2, 4, 0, 2><<<dim3(4, 32), 256, smem_bytes(128, 128, 2, false)>>>(
        dxh, dxl, w0h, w0l, bb0, x1h, x1l, nullptr, nullptr, nullptr, 7, 8, 8, 256);
    gemm_nt_mma<64, 128, 2, 4, 0, 4><<<dim3(2, 64), 256, smem_bytes(64, 128, 4, false)>>>(
        x1h, x1l, w1h, w1l, bb1, x2h, x2l, nullptr, nullptr, nullptr, 256, 256, 256, 128);
    gemm_nt_mma<32, 64, 2, 4, 0, 4><<<dim3(1, 128), 256, smem_bytes(32, 64, 4, false)>>>(
        x2h, x2l, w2h, w2l, bb2, x3h, x3l, nullptr, nullptr, nullptr, 128, 128, 128, 32);

    // 2) fused gather + interaction -> R (split pairs)
    gather_interact<<<BATCH, 256>>>(lS_o, lS_i, emb);

    // 3) top MLP: T0, then T1 with the final 256->1 layer fused in
    gemm_nt_mma<128, 128, 2, 4, 0, 4><<<dim3(4, 32), 256, smem_bytes(128, 128, 4, false)>>>(
        Rh, Rl, t0h, t0l, tb0, z1h, z1l, nullptr, nullptr, nullptr, RP, RP, RP, 256);
    gemm_nt_mma<32, 256, 2, 4, 2, 3><<<dim3(1, 128), 256, smem_bytes(32, 256, 3, true)>>>(
        z1h, z1l, t1h, t1l, tb1, nullptr, nullptr, out, tw2, tb2, 256, 256, 256, 0);
}

// round 15
// speedup vs baseline: 1.1356x; 1.0010x over previous
#include <cuda_runtime.h>
#include <cuda_bf16.h>
#include <math.h>
#include <stdint.h>

#define BATCH 4096
#define NTAB 26
#define VOCAB 100000
#define EMBD 64
#define NT1 27
#define NPAIR 351
#define RP 208            // pairs per R row
#define SROW 36           // interact smem row stride (u32)
#define SROWG 20          // gemm smem row stride (u32): 16 pairs + 4 pad
#define NBLK 128          // uniform grid for mega kernels

// ---- pre-split weight / input buffers (hi/lo bf16x2 pairs) ----
__device__ uint32_t g_dxh[BATCH * 8],  g_dxl[BATCH * 8];
__device__ uint32_t g_w0h[512 * 8],    g_w0l[512 * 8];
__device__ uint32_t g_w1h[256 * 256],  g_w1l[256 * 256];
__device__ uint32_t g_w2h[64 * 128],   g_w2l[64 * 128];
__device__ uint32_t g_t0h[512 * 208],  g_t0l[512 * 208];
__device__ uint32_t g_t1h[256 * 256],  g_t1l[256 * 256];
// ---- split activations ----
__device__ uint32_t g_x1h[BATCH * 256], g_x1l[BATCH * 256];
__device__ uint32_t g_x2h[BATCH * 128], g_x2l[BATCH * 128];
__device__ uint32_t g_x3h[BATCH * 32],  g_x3l[BATCH * 32];
__device__ uint32_t g_Rh [BATCH * RP],  g_Rl [BATCH * RP];
__device__ uint32_t g_z1h[BATCH * 256], g_z1l[BATCH * 256];
__device__ float    g_z2 [BATCH * 256];
// ---- grid-barrier counters (monotonic; never reset -> replay-safe) ----
__device__ unsigned g_bar_bot;
__device__ unsigned g_bar_top;

__device__ __forceinline__ uint32_t pack_bf16x2(float lo, float hi)
{
    __nv_bfloat162 p = __floats2bfloat162_rn(lo, hi);
    return *reinterpret_cast<uint32_t*>(&p);
}
__device__ __forceinline__ float bf16_round(float v)
{
    return __bfloat162float(__float2bfloat16(v));
}
__device__ __forceinline__ void mma_bf16(float* c, const uint32_t* a, const uint32_t* b)
{
    asm volatile(
        "mma.sync.aligned.m16n8k16.row.col.f32.bf16.bf16.f32 "
        "{%0,%1,%2,%3}, {%4,%5,%6,%7}, {%8,%9}, {%0,%1,%2,%3};"
        : "+f"(c[0]), "+f"(c[1]), "+f"(c[2]), "+f"(c[3])
        : "r"(a[0]), "r"(a[1]), "r"(a[2]), "r"(a[3]), "r"(b[0]), "r"(b[1]));
}
__device__ __forceinline__ void ldm_x4(uint32_t* r, const uint32_t* p)
{
    uint32_t a = (uint32_t)__cvta_generic_to_shared(p);
    asm volatile("ldmatrix.sync.aligned.m8n8.x4.shared.b16 {%0,%1,%2,%3}, [%4];"
        : "=r"(r[0]), "=r"(r[1]), "=r"(r[2]), "=r"(r[3]) : "r"(a));
}
__device__ __forceinline__ void cp16(const uint32_t* dst, const uint32_t* src, int bytes)
{
    uint32_t d = (uint32_t)__cvta_generic_to_shared(dst);
    asm volatile("cp.async.cg.shared.global [%0], [%1], 16, %2;\n"
                 :: "r"(d), "l"(src), "r"(bytes));
}
__device__ __forceinline__ void cp_commit() { asm volatile("cp.async.commit_group;\n"); }
template<int N>
__device__ __forceinline__ void cp_wait() { asm volatile("cp.async.wait_group %0;\n" :: "n"(N)); }

// Software grid barrier: all NBLK blocks resident (1 block/SM). Monotonic
// counter; each consecutive group of NBLK arrivals = one barrier instance.
__device__ __forceinline__ void grid_barrier(unsigned* cnt)
{
    __syncthreads();
    if (threadIdx.x == 0) {
        __threadfence();
        unsigned arrival = atomicAdd(cnt, 1u) + 1u;
        unsigned target  = ((arrival + NBLK - 1u) / NBLK) * NBLK;
        while (atomicAdd(cnt, 0u) < target) { }
        __threadfence();
    }
    __syncthreads();
}

// ---------------------------------------------------------------------------
// Split dense_x + 5 weight matrices into bf16 hi/lo pair arrays.
// ---------------------------------------------------------------------------
__global__ __launch_bounds__(256)
void split_all(const float* __restrict__ dx, const float* __restrict__ w0,
               const float* __restrict__ w1, const float* __restrict__ w2,
               const float* __restrict__ t0, const float* __restrict__ t1)
{
    int i = blockIdx.x * 256 + threadIdx.x;
    if (i >= 282624) return;
    const float* src; uint32_t *dh, *dl; int K, P, local;
    if (i < 32768)       { src = dx; dh = g_dxh; dl = g_dxl; K = 13;  P = 8;   local = i; }
    else if (i < 36864)  { src = w0; dh = g_w0h; dl = g_w0l; K = 13;  P = 8;   local = i - 32768; }
    else if (i < 102400) { src = w1; dh = g_w1h; dl = g_w1l; K = 512; P = 256; local = i - 36864; }
    else if (i < 110592) { src = w2; dh = g_w2h; dl = g_w2l; K = 256; P = 128; local = i - 102400; }
    else if (i < 217088) { src = t0; dh = g_t0h; dl = g_t0l; K = 415; P = 208; local = i - 110592; }
    else                 { src = t1; dh = g_t1h; dl = g_t1l; K = 512; P = 256; local = i - 217088; }
    int row = local / P, p = local - row * P, k = 2 * p;
    float v0 = (k     < K) ? src[(size_t)row * K + k]     : 0.f;
    float v1 = (k + 1 < K) ? src[(size_t)row * K + k + 1] : 0.f;
    float h0 = bf16_round(v0), h1 = bf16_round(v1);
    dh[local] = pack_bf16x2(h0, h1);
    dl[local] = pack_bf16x2(v0 - h0, v1 - h1);
}

// ---------------------------------------------------------------------------
// GEMM tile device function: one BMxBN tile of C = relu(A @ W^T + bias).
// STAGES-deep cp.async pipeline, 3-pass hh+hl+lh fp32 accumulation.
// SPLIT_OUT: true -> split-pair output (Ch/Cl, ldc in pairs);
//            false -> fp32 output (Cf, ldc in elems).
// ---------------------------------------------------------------------------
template<int BM, int BN, int WM_, int WN_, bool SPLIT_OUT, int STAGES>
__device__ void gemm_tile(const uint32_t* __restrict__ Ah, const uint32_t* __restrict__ Al,
                          const uint32_t* __restrict__ Wh, const uint32_t* __restrict__ Wl,
                          const float* __restrict__ bias,
                          uint32_t* __restrict__ Ch, uint32_t* __restrict__ Cl,
                          float* __restrict__ Cf,
                          int Kp, int ldap, int ldwp, int ldc,
                          int bm, int bn, uint32_t* dyn)
{
    constexpr int TM  = BM / WM_;
    constexpr int TN  = BN / WN_;
    constexpr int MT  = TM / 16;
    constexpr int NTT = TN / 8;
    constexpr int NT2 = NTT / 2;
    constexpr int STG  = BM * SROWG;
    constexpr int STGW = BN * SROWG;

    uint32_t* sHA = dyn;
    uint32_t* sLA = sHA + STAGES * STG;
    uint32_t* sHW = sLA + STAGES * STG;
    uint32_t* sLW = sHW + STAGES * STGW;

    const int tid  = threadIdx.x;
    const int lane = tid & 31;
    const int wid  = tid >> 5;
    const int wm   = wid % WM_;
    const int wn   = wid / WM_;
    const int g    = lane >> 2;
    const int tg   = lane & 3;

    const int sub_r  = lane & 7;
    const int quad   = lane >> 3;
    const int lm_row = sub_r + (quad & 1) * 8;
    const int lm_col = (quad >> 1) * 4;

    float acc[MT][NTT][4];
    #pragma unroll
    for (int i = 0; i < MT; i++)
        #pragma unroll
        for (int j = 0; j < NTT; j++)
            #pragma unroll
            for (int q = 0; q < 4; q++) acc[i][j][q] = 0.f;

    const int ntiles = (Kp + 15) / 16;

    auto load_stage = [&](int t, int s) {
        uint32_t* dHA = sHA + s * STG;
        uint32_t* dLA = sLA + s * STG;
        uint32_t* dHW = sHW + s * STGW;
        uint32_t* dLW = sLW + s * STGW;
        for (int i = tid; i < BM * 4; i += 256) {
            int row = i >> 2, c = i & 3;
            int gp = t * 16 + c * 4;
            int avail = (ldap - gp) * 4;
            avail = avail < 0 ? 0 : (avail > 16 ? 16 : avail);
            int gpc = gp < ldap - 4 ? gp : ldap - 4;
            size_t goff = (size_t)(bm + row) * ldap + gpc;
            cp16(dHA + row * SROWG + c * 4, Ah + goff, avail);
            cp16(dLA + row * SROWG + c * 4, Al + goff, avail);
        }
        for (int i = tid; i < BN * 4; i += 256) {
            int row = i >> 2, c = i & 3;
            int gp = t * 16 + c * 4;
            int avail = (ldwp - gp) * 4;
            avail = avail < 0 ? 0 : (avail > 16 ? 16 : avail);
            int gpc = gp < ldwp - 4 ? gp : ldwp - 4;
            size_t goff = (size_t)(bn + row) * ldwp + gpc;
            cp16(dHW + row * SROWG + c * 4, Wh + goff, avail);
            cp16(dLW + row * SROWG + c * 4, Wl + goff, avail);
        }
        cp_commit();
    };

    #pragma unroll
    for (int s = 0; s < STAGES - 1; s++) {
        if (s < ntiles) load_stage(s, s); else cp_commit();
    }

    for (int t = 0; t < ntiles; t++) {
        cp_wait<STAGES - 2>();
        __syncthreads();
        {
            int nt_ = t + STAGES - 1;
            if (nt_ < ntiles) load_stage(nt_, nt_ % STAGES); else cp_commit();
        }

        const int s = t % STAGES;
        const uint32_t* bHA = sHA + s * STG;
        const uint32_t* bLA = sLA + s * STG;
        const uint32_t* bHW = sHW + s * STGW;
        const uint32_t* bLW = sLW + s * STGW;

        #pragma unroll
        for (int ks = 0; ks < 2; ks++) {
            const int cb = ks * 8;
            uint32_t ah[MT][4], al[MT][4], bh[NTT][2], bl[NTT][2];
            #pragma unroll
            for (int mt = 0; mt < MT; mt++) {
                int base = (wm * TM + mt * 16 + lm_row) * SROWG + cb + lm_col;
                ldm_x4(ah[mt], &bHA[base]);
                ldm_x4(al[mt], &bLA[base]);
            }
            #pragma unroll
            for (int n2 = 0; n2 < NT2; n2++) {
                int base = (wn * TN + n2 * 16 + lm_row) * SROWG + cb + lm_col;
                uint32_t q[4];
                ldm_x4(q, &bHW[base]);
                bh[2 * n2][0] = q[0]; bh[2 * n2 + 1][0] = q[1];
                bh[2 * n2][1] = q[2]; bh[2 * n2 + 1][1] = q[3];
                ldm_x4(q, &bLW[base]);
                bl[2 * n2][0] = q[0]; bl[2 * n2 + 1][0] = q[1];
                bl[2 * n2][1] = q[2]; bl[2 * n2 + 1][1] = q[3];
            }
            #pragma unroll
            for (int mt = 0; mt < MT; mt++)
                #pragma unroll
                for (int nt = 0; nt < NTT; nt++) {
                    mma_bf16(acc[mt][nt], ah[mt], bh[nt]);
                    mma_bf16(acc[mt][nt], ah[mt], bl[nt]);
                    mma_bf16(acc[mt][nt], al[mt], bh[nt]);
                }
        }
        __syncthreads();
    }
    cp_wait<0>();   // drain empty groups before smem reuse in next phase

    #pragma unroll
    for (int mt = 0; mt < MT; mt++) {
        int r0 = bm + wm * TM + mt * 16 + g;
        #pragma unroll
        for (int nt = 0; nt < NTT; nt++) {
            int col = bn + wn * TN + nt * 8 + tg * 2;
            float bi0 = bias[col], bi1 = bias[col + 1];
            float v0 = fmaxf(acc[mt][nt][0] + bi0, 0.f);
            float v1 = fmaxf(acc[mt][nt][1] + bi1, 0.f);
            float v2 = fmaxf(acc[mt][nt][2] + bi0, 0.f);
            float v3 = fmaxf(acc[mt][nt][3] + bi1, 0.f);
            if (SPLIT_OUT) {
                int pj = col >> 1;
                float h0 = bf16_round(v0), h1 = bf16_round(v1);
                Ch[(size_t)r0 * ldc + pj] = pack_bf16x2(h0, h1);
                Cl[(size_t)r0 * ldc + pj] = pack_bf16x2(v0 - h0, v1 - h1);
                float h2 = bf16_round(v2), h3 = bf16_round(v3);
                Ch[(size_t)(r0 + 8) * ldc + pj] = pack_bf16x2(h2, h3);
                Cl[(size_t)(r0 + 8) * ldc + pj] = pack_bf16x2(v2 - h2, v3 - h3);
            } else {
                Cf[(size_t)r0 * ldc + col]           = v0;
                Cf[(size_t)r0 * ldc + col + 1]       = v1;
                Cf[(size_t)(r0 + 8) * ldc + col]     = v2;
                Cf[(size_t)(r0 + 8) * ldc + col + 1] = v3;
            }
        }
    }
}

// ---------------------------------------------------------------------------
// Mega-kernels: GEMM chains with grid barriers (grid = 128, 1 block/SM).
// ---------------------------------------------------------------------------
__global__ __launch_bounds__(256)
void mega_bottom(const float* __restrict__ bb0, const float* __restrict__ bb1,
                 const float* __restrict__ bb2)
{
    extern __shared__ __align__(16) uint32_t dyn[];
    const int bid = blockIdx.x;

    // L0: 4096x512 @ K13   (grid was (4,32))
    gemm_tile<128, 128, 2, 4, true, 2>(g_dxh, g_dxl, g_w0h, g_w0l, bb0,
        g_x1h, g_x1l, nullptr, 7, 8, 8, 256, (bid >> 2) * 128, (bid & 3) * 128, dyn);
    grid_barrier(&g_bar_bot);

    // L1: 4096x256 @ K512  (grid was (2,64))
    gemm_tile<64, 128, 2, 4, true, 4>(g_x1h, g_x1l, g_w1h, g_w1l, bb1,
        g_x2h, g_x2l, nullptr, 256, 256, 256, 128, (bid >> 1) * 64, (bid & 1) * 128, dyn);
    grid_barrier(&g_bar_bot);

    // L2: 4096x64 @ K256   (grid was (1,128))
    gemm_tile<32, 64, 2, 4, true, 4>(g_x2h, g_x2l, g_w2h, g_w2l, bb2,
        g_x3h, g_x3l, nullptr, 128, 128, 128, 32, bid * 32, 0, dyn);
}

__global__ __launch_bounds__(256)
void mega_top(const float* __restrict__ tb0, const float* __restrict__ tb1,
              const float* __restrict__ tw2, const float* __restrict__ tb2,
              float* __restrict__ out)
{
    extern __shared__ __align__(16) uint32_t dyn[];
    const int bid  = blockIdx.x;
    const int lane = threadIdx.x & 31;
    const int wid  = threadIdx.x >> 5;

    // T0: 4096x512 @ K415
    gemm_tile<128, 128, 2, 4, true, 4>(g_Rh, g_Rl, g_t0h, g_t0l, tb0,
        g_z1h, g_z1l, nullptr, RP, RP, RP, 256, (bid >> 2) * 128, (bid & 3) * 128, dyn);
    grid_barrier(&g_bar_top);

    // T1: 4096x256 @ K512 -> fp32 z2
    gemm_tile<64, 128, 2, 4, false, 4>(g_z1h, g_z1l, g_t1h, g_t1l, tb1,
        nullptr, nullptr, g_z2, 256, 256, 256, 256, (bid >> 1) * 64, (bid & 1) * 128, dyn);
    grid_barrier(&g_bar_top);

    // final: out[b] = sigmoid(dot(z2[b], tw2) + tb2); 32 rows per block
    float fb0 = __ldg(tb2);
    #pragma unroll
    for (int rr = 0; rr < 4; rr++) {
        int b = bid * 32 + wid * 4 + rr;
        const float* z = g_z2 + (size_t)b * 256;
        float s = 0.f;
        #pragma unroll
        for (int k = lane; k < 256; k += 32) s = fmaf(z[k], __ldg(tw2 + k), s);
        #pragma unroll
        for (int o = 16; o; o >>= 1) s += __shfl_xor_sync(0xFFFFFFFFu, s, o);
        if (lane == 0) out[b] = 1.f / (1.f + expf(-(s + fb0)));
    }
}

// ---------------------------------------------------------------------------
// Fused embedding-gather + interaction (split-pair I/O). Unchanged from R12.
// ---------------------------------------------------------------------------
__global__ __launch_bounds__(256)
void gather_interact(const int* __restrict__ lS_o,
                     const int* __restrict__ lS_i,
                     const float* __restrict__ emb)
{
    __shared__ uint32_t sH[32 * SROW];
    __shared__ uint32_t sL[32 * SROW];
    __shared__ float    sZ[NPAIR];
    __shared__ int s_beg[NTAB];
    __shared__ int s_len[NTAB];
    __shared__ int s_idx[NTAB];

    const int b    = blockIdx.x;
    const int tid  = threadIdx.x;
    const int lane = tid & 31;
    const int wid  = tid >> 5;

    if (tid < NTAB) {
        int beg = lS_o[tid * BATCH + b];
        int end = (b + 1 < BATCH) ? lS_o[tid * BATCH + b + 1] : BATCH;
        s_beg[tid] = beg;
        s_len[tid] = end - beg;
        s_idx[tid] = (end - beg == 1) ? __ldg(lS_i + tid * BATCH + beg) : -1;
    }
    if (tid < 32) {
        sH[tid] = g_x3h[(size_t)b * 32 + tid];
        sL[tid] = g_x3l[(size_t)b * 32 + tid];
    }
    __syncthreads();

    {
        const int t0 = tid >> 4;
        const int q  = tid & 15;
        const int t1 = t0 + 16;
        const bool has1 = (t1 < NTAB);

        const float* tab0 = emb + (size_t)t0 * VOCAB * EMBD + q * 4;
        const float* tab1 = emb + (size_t)t1 * VOCAB * EMBD + q * 4;

        float4 a0 = make_float4(0.f, 0.f, 0.f, 0.f);
        float4 a1 = make_float4(0.f, 0.f, 0.f, 0.f);

        int i0f = s_idx[t0];
        int i1f = has1 ? s_idx[t1] : 0;

        if (i0f >= 0 && i1f >= 0) {
            if (has1) {
                float4 v0 = *reinterpret_cast<const float4*>(tab0 + (size_t)i0f * EMBD);
                float4 v1 = *reinterpret_cast<const float4*>(tab1 + (size_t)i1f * EMBD);
                a0 = v0; a1 = v1;
            } else {
                a0 = *reinterpret_cast<const float4*>(tab0 + (size_t)i0f * EMBD);
            }
        } else {
            int p0 = s_beg[t0], e0 = p0 + s_len[t0];
            int p1 = has1 ? s_beg[t1] : 0;
            int e1 = has1 ? (p1 + s_len[t1]) : 0;
            while (p0 < e0 || p1 < e1) {
                int i0 = (p0 < e0) ? __ldg(lS_i + t0 * BATCH + p0) : -1;
                int i1 = (p1 < e1) ? __ldg(lS_i + t1 * BATCH + p1) : -1;
                if (i0 >= 0) {
                    float4 v = *reinterpret_cast<const float4*>(tab0 + (size_t)i0 * EMBD);
                    a0.x += v.x; a0.y += v.y; a0.z += v.z; a0.w += v.w;
                    p0++;
                }
                if (i1 >= 0) {
                    float4 v = *reinterpret_cast<const float4*>(tab1 + (size_t)i1 * EMBD);
                    a1.x += v.x; a1.y += v.y; a1.z += v.z; a1.w += v.w;
                    p1++;
                }
            }
        }

        {
            float hx = bf16_round(a0.x), hy = bf16_round(a0.y);
            float hz = bf16_round(a0.z), hw = bf16_round(a0.w);
            int base = (t0 + 1) * SROW + q * 2;
            sH[base]     = pack_bf16x2(hx, hy);
            sL[base]     = pack_bf16x2(a0.x - hx, a0.y - hy);
            sH[base + 1] = pack_bf16x2(hz, hw);
            sL[base + 1] = pack_bf16x2(a0.z - hz, a0.w - hw);
        }
        if (has1) {
            float hx = bf16_round(a1.x), hy = bf16_round(a1.y);
            float hz = bf16_round(a1.z), hw = bf16_round(a1.w);
            int base = (t1 + 1) * SROW + q * 2;
            sH[base]     = pack_bf16x2(hx, hy);
            sL[base]     = pack_bf16x2(a1.x - hx, a1.y - hy);
            sH[base + 1] = pack_bf16x2(hz, hw);
            sL[base + 1] = pack_bf16x2(a1.z - hz, a1.w - hw);
        }
    }
    __syncthreads();

    const int g  = lane >> 2;
    const int tg = lane & 3;
    const int wm = wid & 1;
    const int wn = wid >> 1;

    float acc[4] = {0.f, 0.f, 0.f, 0.f};
    const int r0 = wm * 16 + g;
    const int r1 = r0 + 8;
    const int nb = wn * 8 + g;

    #pragma unroll
    for (int ks = 0; ks < 4; ks++) {
        int kp = ks * 8 + tg;
        uint32_t ah[4], al[4], bh[2], bl[2];
        ah[0] = sH[r0 * SROW + kp];     al[0] = sL[r0 * SROW + kp];
        ah[1] = sH[r1 * SROW + kp];     al[1] = sL[r1 * SROW + kp];
        ah[2] = sH[r0 * SROW + kp + 4]; al[2] = sL[r0 * SROW + kp + 4];
        ah[3] = sH[r1 * SROW + kp + 4]; al[3] = sL[r1 * SROW + kp + 4];
        bh[0] = sH[nb * SROW + kp];     bl[0] = sL[nb * SROW + kp];
        bh[1] = sH[nb * SROW + kp + 4]; bl[1] = sL[nb * SROW + kp + 4];
        mma_bf16(acc, ah, bh);
        mma_bf16(acc, ah, bl);
        mma_bf16(acc, al, bh);
    }

    {
        int row = wm * 16 + g;
        int col = wn * 8 + tg * 2;
        if (row < NT1) {
            int base = row * (row - 1) / 2;
            if (col     < row) sZ[base + col]     = acc[0];
            if (col + 1 < row) sZ[base + col + 1] = acc[1];
        }
        int row2 = row + 8;
        if (row2 < NT1) {
            int base = row2 * (row2 - 1) / 2;
            if (col     < row2) sZ[base + col]     = acc[2];
            if (col + 1 < row2) sZ[base + col + 1] = acc[3];
        }
    }
    __syncthreads();

    uint32_t* Rh = g_Rh + (size_t)b * RP;
    uint32_t* Rl = g_Rl + (size_t)b * RP;
    for (int pj = tid; pj < RP; pj += 256) {
        if (pj < 32) {
            Rh[pj] = g_x3h[(size_t)b * 32 + pj];
            Rl[pj] = g_x3l[(size_t)b * 32 + pj];
        } else {
            int e0 = 2 * pj - 64;
            float v0 = sZ[e0];
            float v1 = (e0 + 1 < NPAIR) ? sZ[e0 + 1] : 0.f;
            float h0 = bf16_round(v0), h1 = bf16_round(v1);
            Rh[pj] = pack_bf16x2(h0, h1);
            Rl[pj] = pack_bf16x2(v0 - h0, v1 - h1);
        }
    }
}

// ---------------------------------------------------------------------------
static inline int smem_bytes(int BM, int BN, int stages)
{
    return stages * (2 * BM + 2 * BN) * SROWG * 4;
}

extern "C" void kernel_launch(void* const* d_in, const int* in_sizes, int n_in,
                              void* d_out, int out_size)
{
    const float* dense_x = (const float*)d_in[0];
    const int*   lS_o    = (const int*)  d_in[1];
    const int*   lS_i    = (const int*)  d_in[2];
    const float* emb     = (const float*)d_in[3];
    const float* bw0     = (const float*)d_in[4];
    const float* bb0     = (const float*)d_in[5];
    const float* bw1     = (const float*)d_in[6];
    const float* bb1     = (const float*)d_in[7];
    const float* bw2     = (const float*)d_in[8];
    const float* bb2     = (const float*)d_in[9];
    const float* tw0     = (const float*)d_in[10];
    const float* tb0     = (const float*)d_in[11];
    const float* tw1     = (const float*)d_in[12];
    const float* tb1     = (const float*)d_in[13];
    const float* tw2     = (const float*)d_in[14];
    const float* tb2     = (const float*)d_in[15];
    float* out = (float*)d_out;

    // max smem per mega kernel
    const int smem_bot = smem_bytes(64, 128, 4);    // 122880 (covers L0's 81920, L2's 61440)
    const int smem_top = smem_bytes(128, 128, 4);   // 163840 (covers T1's 122880)

    cudaFuncSetAttribute(mega_bottom, cudaFuncAttributeMaxDynamicSharedMemorySize, smem_bot);
    cudaFuncSetAttribute(mega_top,    cudaFuncAttributeMaxDynamicSharedMemorySize, smem_top);

    // 0) split inputs/weights
    split_all<<<(282624 + 255) / 256, 256>>>(dense_x, bw0, bw1, bw2, tw0, tw1);

    // 1) bottom MLP megakernel (L0 -> L1 -> L2)
    mega_bottom<<<NBLK, 256, smem_bot>>>(bb0, bb1, bb2);

    // 2) fused gather + interaction -> R (split pairs)
    gather_interact<<<BATCH, 256>>>(lS_o, lS_i, emb);

    // 3) top MLP megakernel (T0 -> T1 -> final)
    mega_top<<<NBLK, 256, smem_top>>>(tb0, tb1, tw2, tb2, out);
}